// round 1
// baseline (speedup 1.0000x reference)
#include <cuda_runtime.h>
#include <cuda_bf16.h>

#define IMG_S 4096
#define NDOTS 100
#define TILE_W 64
#define TILE_H 32
#define NTHREADS 256

__global__ __launch_bounds__(NTHREADS)
void patch_dots_kernel(const float* __restrict__ patch,
                       const float* __restrict__ centers,
                       const float* __restrict__ radii,
                       const float* __restrict__ colors,
                       float* __restrict__ out)
{
    __shared__ float sxc[NDOTS];
    __shared__ float syc[NDOTS];
    __shared__ float sr2[NDOTS];
    __shared__ float scr[NDOTS];
    __shared__ float scg[NDOTS];
    __shared__ float scb[NDOTS];
    __shared__ unsigned smask[4];

    const int tid = threadIdx.x;

    // Tile origin
    const int tiles_x = IMG_S / TILE_W;       // 64
    const int tx0 = (blockIdx.x % tiles_x) * TILE_W;
    const int ty0 = (blockIdx.x / tiles_x) * TILE_H;

    // ---- Load dot parameters into shared (exactly matching reference fp32 math) ----
    if (tid < NDOTS) {
        float cx = floorf(centers[2 * tid + 0] * (float)IMG_S);
        float cy = floorf(centers[2 * tid + 1] * (float)IMG_S);
        float r  = floorf(radii[tid] * ((float)IMG_S / 5.0f));
        sxc[tid] = cx;
        syc[tid] = cy;
        sr2[tid] = r * r;
        scr[tid] = colors[3 * tid + 0];
        scg[tid] = colors[3 * tid + 1];
        scb[tid] = colors[3 * tid + 2];
    }
    __syncthreads();

    // ---- Cull dots vs this tile's AABB (exact circle-vs-box test) ----
    // Warps 0..3 handle dots 0..127 (dots >= NDOTS -> false).
    if (tid < 128) {
        bool hit = false;
        if (tid < NDOTS) {
            float cx = sxc[tid], cy = syc[tid];
            float px = fminf(fmaxf(cx, (float)tx0), (float)(tx0 + TILE_W - 1));
            float py = fminf(fmaxf(cy, (float)ty0), (float)(ty0 + TILE_H - 1));
            float dx = px - cx, dy = py - cy;
            hit = (dx * dx + dy * dy) <= sr2[tid];
        }
        unsigned m = __ballot_sync(0xFFFFFFFFu, hit);
        if ((tid & 31) == 0) smask[tid >> 5] = m;
    }
    __syncthreads();

    const unsigned m0 = smask[0];
    const unsigned m1 = smask[1];
    const unsigned m2 = smask[2];
    const unsigned m3 = smask[3];

    // ---- Per-pixel: find highest-index covering dot, scanning bits MSB->LSB ----
    const int lx = tid & (TILE_W - 1);   // 0..63  (x within tile)
    const int lyb = tid >> 6;            // 0..3   (row group base)

    const long long plane = (long long)IMG_S * IMG_S;

    #pragma unroll 1
    for (int step = 0; step < TILE_H / 4; ++step) {
        const int x = tx0 + lx;
        const int y = ty0 + lyb + 4 * step;
        const float fx = (float)x;
        const float fy = (float)y;

        int hit = -1;

        // scan descending: word 3 (dots 96..127) down to word 0
        unsigned mm;
        #define SCAN_WORD(MW, BASE)                                        \
            mm = (MW);                                                     \
            while (mm) {                                                   \
                int b = 31 - __clz(mm);                                    \
                int i = (BASE) + b;                                        \
                float dx = fx - sxc[i];                                    \
                float dy = fy - syc[i];                                    \
                if (dx * dx + dy * dy <= sr2[i]) { hit = i; break; }       \
                mm &= ~(1u << b);                                          \
            }

        SCAN_WORD(m3, 96)
        if (hit < 0) { SCAN_WORD(m2, 64) }
        if (hit < 0) { SCAN_WORD(m1, 32) }
        if (hit < 0) { SCAN_WORD(m0, 0)  }
        #undef SCAN_WORD

        const long long idx = (long long)y * IMG_S + x;
        if (hit >= 0) {
            out[idx]             = scr[hit];
            out[idx + plane]     = scg[hit];
            out[idx + 2 * plane] = scb[hit];
        } else {
            out[idx]             = patch[idx];
            out[idx + plane]     = patch[idx + plane];
            out[idx + 2 * plane] = patch[idx + 2 * plane];
        }
    }
}

extern "C" void kernel_launch(void* const* d_in, const int* in_sizes, int n_in,
                              void* d_out, int out_size)
{
    const float* patch   = (const float*)d_in[0];
    const float* centers = (const float*)d_in[1];
    const float* radii   = (const float*)d_in[2];
    const float* colors  = (const float*)d_in[3];
    float* out = (float*)d_out;

    const int tiles = (IMG_S / TILE_W) * (IMG_S / TILE_H);  // 64 * 128 = 8192
    patch_dots_kernel<<<tiles, NTHREADS>>>(patch, centers, radii, colors, out);
}

// round 2
// speedup vs baseline: 1.2112x; 1.2112x over previous
#include <cuda_runtime.h>
#include <cuda_bf16.h>

#define IMG_S 4096
#define NDOTS 100
#define TILE_W 64
#define TILE_H 32
#define NTHREADS 256

__global__ __launch_bounds__(NTHREADS)
void patch_dots_kernel(const float* __restrict__ patch,
                       const float* __restrict__ centers,
                       const float* __restrict__ radii,
                       const float* __restrict__ colors,
                       float* __restrict__ out)
{
    __shared__ float sxc[NDOTS];
    __shared__ float syc[NDOTS];
    __shared__ float sr2[NDOTS];
    __shared__ float scr[NDOTS];
    __shared__ float scg[NDOTS];
    __shared__ float scb[NDOTS];
    __shared__ unsigned smask[4];

    const int tid = threadIdx.x;

    const int tiles_x = IMG_S / TILE_W;       // 64
    const int tx0 = (blockIdx.x % tiles_x) * TILE_W;
    const int ty0 = (blockIdx.x / tiles_x) * TILE_H;

    // ---- Load dot parameters (exactly matching reference fp32 math) ----
    if (tid < NDOTS) {
        float cx = floorf(centers[2 * tid + 0] * (float)IMG_S);
        float cy = floorf(centers[2 * tid + 1] * (float)IMG_S);
        float r  = floorf(radii[tid] * ((float)IMG_S / 5.0f));
        sxc[tid] = cx;
        syc[tid] = cy;
        sr2[tid] = r * r;
        scr[tid] = colors[3 * tid + 0];
        scg[tid] = colors[3 * tid + 1];
        scb[tid] = colors[3 * tid + 2];
    }
    __syncthreads();

    // ---- Cull dots vs tile AABB (exact circle-vs-box) ----
    if (tid < 128) {
        bool hit = false;
        if (tid < NDOTS) {
            float cx = sxc[tid], cy = syc[tid];
            float px = fminf(fmaxf(cx, (float)tx0), (float)(tx0 + TILE_W - 1));
            float py = fminf(fmaxf(cy, (float)ty0), (float)(ty0 + TILE_H - 1));
            float dx = px - cx, dy = py - cy;
            hit = (dx * dx + dy * dy) <= sr2[tid];
        }
        unsigned m = __ballot_sync(0xFFFFFFFFu, hit);
        if ((tid & 31) == 0) smask[tid >> 5] = m;
    }
    __syncthreads();

    const unsigned m0 = smask[0];
    const unsigned m1 = smask[1];
    const unsigned m2 = smask[2];
    const unsigned m3 = smask[3];

    // ---- Per-quad (4 consecutive x pixels per thread) ----
    const int lx = (tid & 15) * 4;        // x offset within tile: 0..60
    const int ly = tid >> 4;              // row within step: 0..15

    const unsigned plane_q = (IMG_S / 4) * IMG_S;   // quads per plane
    const float4* __restrict__ p4 = (const float4*)patch;
    float4* __restrict__ o4 = (float4*)out;

    #pragma unroll
    for (int step = 0; step < TILE_H / 16; ++step) {
        const int x = tx0 + lx;
        const int y = ty0 + ly + 16 * step;
        const float fx = (float)x;
        const float fy = (float)y;

        int hitmask = 0;
        float cr0, cr1, cr2, cr3;
        float cg0, cg1, cg2, cg3;
        float cb0, cb1, cb2, cb3;

        unsigned mm;
        #define TEST_LANE(J, DXJ)                                              \
            if (!(hitmask & (1 << J))) {                                       \
                float dx = (DXJ);                                              \
                if (fmaf(dx, dx, dy2) <= r2) {                                 \
                    hitmask |= (1 << J);                                       \
                    cr##J = cri; cg##J = cgi; cb##J = cbi;                     \
                }                                                              \
            }

        #define SCAN_WORD(MW, BASE)                                           \
            mm = (MW);                                                         \
            while (mm) {                                                       \
                int b = 31 - __clz(mm);                                        \
                int i = (BASE) + b;                                            \
                float dy = fy - syc[i];                                        \
                float dy2 = dy * dy;                                           \
                float r2  = sr2[i];                                            \
                float xci = sxc[i];                                            \
                float cri = scr[i], cgi = scg[i], cbi = scb[i];                \
                float dx0 = fx - xci;                                          \
                TEST_LANE(0, dx0)                                              \
                TEST_LANE(1, dx0 + 1.0f)                                       \
                TEST_LANE(2, dx0 + 2.0f)                                       \
                TEST_LANE(3, dx0 + 3.0f)                                       \
                if (hitmask == 0xF) break;                                     \
                mm &= ~(1u << b);                                              \
            }

        SCAN_WORD(m3, 96)
        if (hitmask != 0xF) { SCAN_WORD(m2, 64) }
        if (hitmask != 0xF) { SCAN_WORD(m1, 32) }
        if (hitmask != 0xF) { SCAN_WORD(m0, 0)  }
        #undef SCAN_WORD
        #undef TEST_LANE

        const unsigned qidx = (unsigned)(y * (IMG_S / 4) + (x >> 2));

        if (hitmask == 0xF) {
            o4[qidx]               = make_float4(cr0, cr1, cr2, cr3);
            o4[qidx + plane_q]     = make_float4(cg0, cg1, cg2, cg3);
            o4[qidx + 2 * plane_q] = make_float4(cb0, cb1, cb2, cb3);
        } else {
            float4 pr = p4[qidx];
            float4 pg = p4[qidx + plane_q];
            float4 pb = p4[qidx + 2 * plane_q];
            if (!(hitmask & 1)) { cr0 = pr.x; cg0 = pg.x; cb0 = pb.x; }
            if (!(hitmask & 2)) { cr1 = pr.y; cg1 = pg.y; cb1 = pb.y; }
            if (!(hitmask & 4)) { cr2 = pr.z; cg2 = pg.z; cb2 = pb.z; }
            if (!(hitmask & 8)) { cr3 = pr.w; cg3 = pg.w; cb3 = pb.w; }
            o4[qidx]               = make_float4(cr0, cr1, cr2, cr3);
            o4[qidx + plane_q]     = make_float4(cg0, cg1, cg2, cg3);
            o4[qidx + 2 * plane_q] = make_float4(cb0, cb1, cb2, cb3);
        }
    }
}

extern "C" void kernel_launch(void* const* d_in, const int* in_sizes, int n_in,
                              void* d_out, int out_size)
{
    const float* patch   = (const float*)d_in[0];
    const float* centers = (const float*)d_in[1];
    const float* radii   = (const float*)d_in[2];
    const float* colors  = (const float*)d_in[3];
    float* out = (float*)d_out;

    const int tiles = (IMG_S / TILE_W) * (IMG_S / TILE_H);  // 8192
    patch_dots_kernel<<<tiles, NTHREADS>>>(patch, centers, radii, colors, out);
}

// round 3
// speedup vs baseline: 1.2487x; 1.0310x over previous
#include <cuda_runtime.h>
#include <cuda_bf16.h>

#define IMG_S 4096
#define NDOTS 100
#define TILE_W 64
#define TILE_H 16
#define NTHREADS 256

__global__ __launch_bounds__(NTHREADS)
void patch_dots_kernel(const float* __restrict__ patch,
                       const float* __restrict__ centers,
                       const float* __restrict__ radii,
                       const float* __restrict__ colors,
                       float* __restrict__ out)
{
    __shared__ float sxc[NDOTS];
    __shared__ float syc[NDOTS];
    __shared__ float sr2[NDOTS];
    __shared__ float scr[NDOTS];
    __shared__ float scg[NDOTS];
    __shared__ float scb[NDOTS];
    __shared__ unsigned s_isect[4];   // circle intersects tile AABB
    __shared__ unsigned s_full[4];    // circle fully contains tile

    const int tid = threadIdx.x;

    const int tiles_x = IMG_S / TILE_W;       // 64
    const int tx0 = (blockIdx.x % tiles_x) * TILE_W;
    const int ty0 = (blockIdx.x / tiles_x) * TILE_H;

    // ---- Load dot parameters (exactly matching reference fp32 math) ----
    if (tid < NDOTS) {
        float cx = floorf(centers[2 * tid + 0] * (float)IMG_S);
        float cy = floorf(centers[2 * tid + 1] * (float)IMG_S);
        float r  = floorf(radii[tid] * ((float)IMG_S / 5.0f));
        sxc[tid] = cx;
        syc[tid] = cy;
        sr2[tid] = r * r;
        scr[tid] = colors[3 * tid + 0];
        scg[tid] = colors[3 * tid + 1];
        scb[tid] = colors[3 * tid + 2];
    }
    __syncthreads();

    // ---- Cull: intersect test (nearest point) + full-cover test (farthest corner) ----
    if (tid < 128) {
        bool isect = false, full = false;
        if (tid < NDOTS) {
            float cx = sxc[tid], cy = syc[tid], r2 = sr2[tid];
            float x0 = (float)tx0, x1 = (float)(tx0 + TILE_W - 1);
            float y0 = (float)ty0, y1 = (float)(ty0 + TILE_H - 1);
            // nearest point in box to center
            float nx = fminf(fmaxf(cx, x0), x1) - cx;
            float ny = fminf(fmaxf(cy, y0), y1) - cy;
            isect = (nx * nx + ny * ny) <= r2;
            // farthest corner of box from center
            float fxd = fmaxf(fabsf(x0 - cx), fabsf(x1 - cx));
            float fyd = fmaxf(fabsf(y0 - cy), fabsf(y1 - cy));
            full = (fxd * fxd + fyd * fyd) <= r2;
        }
        unsigned mi = __ballot_sync(0xFFFFFFFFu, isect);
        unsigned mf = __ballot_sync(0xFFFFFFFFu, full);
        if ((tid & 31) == 0) { s_isect[tid >> 5] = mi; s_full[tid >> 5] = mf; }
    }
    __syncthreads();

    unsigned m0 = s_isect[0], m1 = s_isect[1], m2 = s_isect[2], m3 = s_isect[3];
    const unsigned f0 = s_full[0], f1 = s_full[1], f2 = s_full[2], f3 = s_full[3];

    // Highest full-covering dot shadows everything below it.
    int jmax = -1;
    if (f3)      jmax = 96 + (31 - __clz(f3));
    else if (f2) jmax = 64 + (31 - __clz(f2));
    else if (f1) jmax = 32 + (31 - __clz(f1));
    else if (f0) jmax =      (31 - __clz(f0));

    const bool tile_full = (jmax >= 0);
    if (tile_full) {
        // clear all bits below jmax (those dots can never be the answer here)
        if (jmax >= 96)      { m0 = m1 = m2 = 0; m3 &= 0xFFFFFFFFu << (jmax - 96); }
        else if (jmax >= 64) { m0 = m1 = 0;      m2 &= 0xFFFFFFFFu << (jmax - 64); }
        else if (jmax >= 32) { m0 = 0;           m1 &= 0xFFFFFFFFu << (jmax - 32); }
        else                 {                   m0 &= 0xFFFFFFFFu <<  jmax;       }
    }

    // ---- One quad (4 consecutive x pixels) per thread ----
    const int lx = (tid & 15) * 4;        // 0..60
    const int ly = tid >> 4;              // 0..15

    const unsigned plane_q = (IMG_S / 4) * IMG_S;
    const float4* __restrict__ p4 = (const float4*)patch;
    float4* __restrict__ o4 = (float4*)out;

    const int x = tx0 + lx;
    const int y = ty0 + ly;
    const float fx = (float)x;
    const float fy = (float)y;
    const unsigned qidx = (unsigned)(y * (IMG_S / 4) + (x >> 2));

    // Prefetch patch only when the tile isn't fully covered (rare path);
    // issued before the scan so DRAM latency overlaps compute.
    float4 pr, pg, pb;
    if (!tile_full) {
        pr = p4[qidx];
        pg = p4[qidx + plane_q];
        pb = p4[qidx + 2 * plane_q];
    }

    int hitmask = 0;
    float cr0, cr1, cr2, cr3;
    float cg0, cg1, cg2, cg3;
    float cb0, cb1, cb2, cb3;

    unsigned mm;
    #define TEST_LANE(J, DXJ)                                              \
        if (!(hitmask & (1 << J))) {                                       \
            float dx = (DXJ);                                              \
            if (fmaf(dx, dx, dy2) <= r2) {                                 \
                hitmask |= (1 << J);                                       \
                cr##J = cri; cg##J = cgi; cb##J = cbi;                     \
            }                                                              \
        }

    #define SCAN_WORD(MW, BASE)                                           \
        mm = (MW);                                                         \
        while (mm) {                                                       \
            int b = 31 - __clz(mm);                                        \
            int i = (BASE) + b;                                            \
            float dy = fy - syc[i];                                        \
            float dy2 = dy * dy;                                           \
            float r2  = sr2[i];                                            \
            float xci = sxc[i];                                            \
            float cri = scr[i], cgi = scg[i], cbi = scb[i];                \
            float dx0 = fx - xci;                                          \
            TEST_LANE(0, dx0)                                              \
            TEST_LANE(1, dx0 + 1.0f)                                       \
            TEST_LANE(2, dx0 + 2.0f)                                       \
            TEST_LANE(3, dx0 + 3.0f)                                       \
            if (hitmask == 0xF) break;                                     \
            mm &= ~(1u << b);                                              \
        }

    SCAN_WORD(m3, 96)
    if (hitmask != 0xF) { SCAN_WORD(m2, 64) }
    if (hitmask != 0xF) { SCAN_WORD(m1, 32) }
    if (hitmask != 0xF) { SCAN_WORD(m0, 0)  }
    #undef SCAN_WORD
    #undef TEST_LANE

    if (hitmask != 0xF) {
        // only possible when !tile_full — patch quad was prefetched
        if (!(hitmask & 1)) { cr0 = pr.x; cg0 = pg.x; cb0 = pb.x; }
        if (!(hitmask & 2)) { cr1 = pr.y; cg1 = pg.y; cb1 = pb.y; }
        if (!(hitmask & 4)) { cr2 = pr.z; cg2 = pg.z; cb2 = pb.z; }
        if (!(hitmask & 8)) { cr3 = pr.w; cg3 = pg.w; cb3 = pb.w; }
    }

    o4[qidx]               = make_float4(cr0, cr1, cr2, cr3);
    o4[qidx + plane_q]     = make_float4(cg0, cg1, cg2, cg3);
    o4[qidx + 2 * plane_q] = make_float4(cb0, cb1, cb2, cb3);
}

extern "C" void kernel_launch(void* const* d_in, const int* in_sizes, int n_in,
                              void* d_out, int out_size)
{
    const float* patch   = (const float*)d_in[0];
    const float* centers = (const float*)d_in[1];
    const float* radii   = (const float*)d_in[2];
    const float* colors  = (const float*)d_in[3];
    float* out = (float*)d_out;

    const int tiles = (IMG_S / TILE_W) * (IMG_S / TILE_H);  // 64 * 256 = 16384
    patch_dots_kernel<<<tiles, NTHREADS>>>(patch, centers, radii, colors, out);
}